// round 15
// baseline (speedup 1.0000x reference)
#include <cuda_runtime.h>
#include <math.h>
#include <stdint.h>

#define HD 512
#define ND 512
#define BS 8
#define LS 4096
#define NHALF 256
#define NCH 32
#define CHL 128
#define PAD 36
#define ABYTES (128 * PAD * 4)

// Scratch buffers.
__device__ float2 g_bu[(size_t)BS * ND * LS];      // Bu / x-local, [b][n][l]
__device__ float2 g_carry[BS * NCH * ND];
__device__ float2 g_cin[BS * NCH * ND];
__device__ float  g_ut[(size_t)BS * LS * HD];      // tf32-rounded u
__device__ float  g_bt[(size_t)1024 * 512];        // B'[n'=2n+c][h], tf32
__device__ float  g_ct[(size_t)512 * 1024];        // Cc[j][k'=2n+c] = (C0,-C1), tf32
__device__ float2 g_pw[512 * 128];                 // lam_n^(pos+1)

// ---------------------------------------------------------------- helpers ---
__device__ __forceinline__ float tf32r(float f) {
    uint32_t t;
    asm("cvt.rna.tf32.f32 %0, %1;" : "=r"(t) : "f"(f));
    return __uint_as_float(t);
}
__device__ __forceinline__ void mma8(float* d, const uint32_t* a, uint32_t b0, uint32_t b1) {
    asm volatile(
        "mma.sync.aligned.m16n8k8.row.col.f32.tf32.tf32.f32 "
        "{%0,%1,%2,%3}, {%4,%5,%6,%7}, {%8,%9}, {%0,%1,%2,%3};"
        : "+f"(d[0]), "+f"(d[1]), "+f"(d[2]), "+f"(d[3])
        : "r"(a[0]), "r"(a[1]), "r"(a[2]), "r"(a[3]), "r"(b0), "r"(b1));
}
__device__ __forceinline__ void ldsm4(uint32_t* r, uint32_t addr) {
    asm volatile("ldmatrix.sync.aligned.m8n8.x4.shared.b16 {%0,%1,%2,%3}, [%4];"
                 : "=r"(r[0]), "=r"(r[1]), "=r"(r[2]), "=r"(r[3]) : "r"(addr));
}
__device__ __forceinline__ void cpa16(uint32_t dst, const float* src) {
    asm volatile("cp.async.cg.shared.global [%0], [%1], 16;" :: "r"(dst), "l"(src));
}
#define CP_COMMIT() asm volatile("cp.async.commit_group;")
#define CP_WAIT(N)  asm volatile("cp.async.wait_group %0;" :: "n"(N))

__device__ __forceinline__ void lam_of(int n, const float* __restrict__ nu_log,
                                       const float* __restrict__ th_log,
                                       float& lr, float& li) {
    float nu  = expf(nu_log[n]);
    float mag = expf(-nu);
    float th  = expf(th_log[n]);
    float s, c;
    sincosf(th, &s, &c);
    lr = mag * c;
    li = mag * s;
}

// ---------------------------------------------------------------- preps -----
__global__ __launch_bounds__(256)
void prep_u(const float* __restrict__ u) {
    size_t idx = (size_t)blockIdx.x * 256 + threadIdx.x;
#pragma unroll
    for (int i = 0; i < 4; i++) {
        size_t j = idx + (size_t)i * 1048576;
        float4 f = *(const float4*)(u + j * 4);
        float4 o = make_float4(tf32r(f.x), tf32r(f.y), tf32r(f.z), tf32r(f.w));
        *(float4*)(g_ut + j * 4) = o;
    }
}
__global__ __launch_bounds__(256)
void bt_prep(const float* __restrict__ Bw) {
    int idx = blockIdx.x * 256 + threadIdx.x;
    int h  = idx & 511;
    int np = idx >> 9;
    g_bt[(size_t)np * 512 + h] = tf32r(Bw[(size_t)h * 1024 + np]);
}
__global__ __launch_bounds__(256)
void cc_prep(const float* __restrict__ Cw) {
    int idx = blockIdx.x * 256 + threadIdx.x;
    int j  = idx & 511;
    int kp = idx >> 9;
    int n  = kp >> 1, c = kp & 1;
    float v = Cw[(size_t)c * HD * ND + (size_t)n * ND + j];
    g_ct[(size_t)j * 1024 + kp] = tf32r(c ? -v : v);
}
// pw[n][pos] = lam_n^(pos+1)
__global__ __launch_bounds__(256)
void pw_prep(const float* __restrict__ nu_log, const float* __restrict__ th_log) {
    int idx = blockIdx.x * 256 + threadIdx.x;   // 0..65535
    int n = idx >> 7, pos = idx & 127;
    float lr, li;
    lam_of(n, nu_log, th_log, lr, li);
    int e = pos + 1;
    float pr = 1.f, pi = 0.f, qr = lr, qi = li;
#pragma unroll
    for (int bit = 0; bit < 8; bit++) {
        if (e & (1 << bit)) {
            float t2 = pr * qr - pi * qi;
            pi = pr * qi + pi * qr;
            pr = t2;
        }
        float t3 = qr * qr - qi * qi;
        qi = 2.f * qr * qi;
        qr = t3;
    }
    g_pw[n * 128 + pos] = make_float2(pr, pi);
}

// -------- GEMM1 + fused scanA (R11 version: 2-stage ring) -------------------
__global__ __launch_bounds__(256)
void gemm_bu_mma(const int* __restrict__ lengths, const float* __restrict__ nu_log,
                 const float* __restrict__ th_log) {
    extern __shared__ float sm[];
    uint32_t sA = (uint32_t)__cvta_generic_to_shared(sm);
    uint32_t sB = sA + 2 * ABYTES;

    int tid = threadIdx.x, wid = tid >> 5, lane = tid & 31;
    int g = lane >> 2, t = lane & 3;
    int wm = wid >> 1, wn = wid & 1;
    int np0 = blockIdx.x * 128;
    int b   = blockIdx.y >> 5;
    int l0  = (blockIdx.y & 31) * 128;

    const float* ua = g_ut + ((size_t)b * LS + l0) * HD;
    const float* bb = g_bt + (size_t)np0 * 512;

    int lr8 = lane & 7, lm = lane >> 3;
    int rsel = (lm & 1) * 8, csel = (lm >> 1) * 4;
    uint32_t aB[2], bBp[4];
#pragma unroll
    for (int mi = 0; mi < 2; mi++)
        aB[mi] = sA + ((wm * 32 + mi * 16 + rsel + lr8) * PAD + csel) * 4;
#pragma unroll
    for (int p = 0; p < 4; p++)
        bBp[p] = sB + ((wn * 64 + p * 16 + rsel + lr8) * PAD + csel) * 4;

    int crow = tid >> 3, cc4 = tid & 7;

    float acc[2][8][4];
#pragma unroll
    for (int mi = 0; mi < 2; mi++)
#pragma unroll
        for (int ni = 0; ni < 8; ni++)
#pragma unroll
            for (int q = 0; q < 4; q++) acc[mi][ni][q] = 0.f;

#define G1_LOAD(c_, buf_)                                                      \
    {                                                                          \
        int k0_ = (c_) * 32;                                                   \
        uint32_t da_ = sA + (buf_) * ABYTES, db_ = sB + (buf_) * ABYTES;       \
        _Pragma("unroll")                                                      \
        for (int i_ = 0; i_ < 4; i_++) {                                       \
            int r_ = crow + 32 * i_;                                           \
            cpa16(da_ + (r_ * PAD + cc4 * 4) * 4,                              \
                  ua + (size_t)r_ * HD + k0_ + cc4 * 4);                       \
            cpa16(db_ + (r_ * PAD + cc4 * 4) * 4,                              \
                  bb + (size_t)r_ * 512 + k0_ + cc4 * 4);                      \
        }                                                                      \
        CP_COMMIT();                                                           \
    }

    G1_LOAD(0, 0);
    for (int c = 0; c < 16; c++) {
        int buf = c & 1;
        if (c < 15) { G1_LOAD(c + 1, buf ^ 1); CP_WAIT(1); }
        else        { CP_WAIT(0); }
        __syncthreads();
        uint32_t boff = buf * ABYTES;
#pragma unroll
        for (int ks = 0; ks < 4; ks++) {
            int kb4 = ks * 32;
            uint32_t a0[4], a1[4];
            ldsm4(a0, aB[0] + boff + kb4);
            ldsm4(a1, aB[1] + boff + kb4);
#pragma unroll
            for (int p = 0; p < 4; p++) {
                uint32_t bf[4];
                ldsm4(bf, bBp[p] + boff + kb4);
                mma8(acc[0][2 * p],     a0, bf[0], bf[2]);
                mma8(acc[1][2 * p],     a1, bf[0], bf[2]);
                mma8(acc[0][2 * p + 1], a0, bf[1], bf[3]);
                mma8(acc[1][2 * p + 1], a1, bf[1], bf[3]);
            }
        }
        __syncthreads();
    }

    // ---- stage masked (re,im) tile in smem: tile[n_local][l_local] ----
    float2* tile = (float2*)sm;          // 64 rows x stride 132 float2 = 66KB
    int len = lengths[b];
#pragma unroll
    for (int mi = 0; mi < 2; mi++) {
        int l_lo = wm * 32 + mi * 16 + g;
        int l_hi = l_lo + 8;
        bool v0 = (l0 + l_lo) < len, v1 = (l0 + l_hi) < len;
#pragma unroll
        for (int ni = 0; ni < 8; ni++) {
            int nl = wn * 32 + ni * 4 + t;
            tile[nl * 132 + l_lo] = v0 ? make_float2(acc[mi][ni][0], acc[mi][ni][1])
                                       : make_float2(0.f, 0.f);
            tile[nl * 132 + l_hi] = v1 ? make_float2(acc[mi][ni][2], acc[mi][ni][3])
                                       : make_float2(0.f, 0.f);
        }
    }
    __syncthreads();

    // ---- fused scanA: each warp scans 8 n-rows of this 128-l chunk ----
    bool rev = (np0 >= 512);
    int chunkL = rev ? 31 - (l0 >> 7) : (l0 >> 7);
    int nbase = np0 >> 1;
#pragma unroll 1
    for (int r = 0; r < 8; r++) {
        int nl = wid * 8 + r;
        int n  = nbase + nl;
        float lr, li;
        lam_of(n, nu_log, th_log, lr, li);

        const float2* row = &tile[nl * 132];
        float cr[4], ci[4];
        int pbL = 124 - lane * 4;
        if (!rev) {
            float4 f0 = *(const float4*)&row[lane * 4];
            float4 f1 = *(const float4*)&row[lane * 4 + 2];
            cr[0] = f0.x; ci[0] = f0.y; cr[1] = f0.z; ci[1] = f0.w;
            cr[2] = f1.x; ci[2] = f1.y; cr[3] = f1.z; ci[3] = f1.w;
        } else {
            float4 f0 = *(const float4*)&row[pbL];
            float4 f1 = *(const float4*)&row[pbL + 2];
            cr[0] = f1.z; ci[0] = f1.w; cr[1] = f1.x; ci[1] = f1.y;
            cr[2] = f0.z; ci[2] = f0.w; cr[3] = f0.x; ci[3] = f0.y;
        }

        float yr[4], yi[4];
        yr[0] = cr[0]; yi[0] = ci[0];
#pragma unroll
        for (int i = 1; i < 4; i++) {
            yr[i] = fmaf(lr, yr[i - 1], fmaf(-li, yi[i - 1], cr[i]));
            yi[i] = fmaf(lr, yi[i - 1], fmaf( li, yr[i - 1], ci[i]));
        }

        float l2r = lr * lr - li * li, l2i = 2.f * lr * li;
        float fr  = l2r * l2r - l2i * l2i, fi = 2.f * l2r * l2i;

        float sr = yr[3], si = yi[3];
#pragma unroll
        for (int s = 1; s < 32; s <<= 1) {
            float pr_ = __shfl_up_sync(0xffffffffu, sr, s);
            float pi_ = __shfl_up_sync(0xffffffffu, si, s);
            if (lane >= s) {
                sr = fmaf(fr, pr_, fmaf(-fi, pi_, sr));
                si = fmaf(fr, pi_, fmaf( fi, pr_, si));
            }
            float nfr = fr * fr - fi * fi;
            fi = 2.f * fr * fi;
            fr = nfr;
        }
        float car = __shfl_up_sync(0xffffffffu, sr, 1);
        float cai = __shfl_up_sync(0xffffffffu, si, 1);
        if (lane == 0) { car = 0.f; cai = 0.f; }

        float pr = lr, pi = li;
        float xr[4], xi[4];
#pragma unroll
        for (int i = 0; i < 4; i++) {
            xr[i] = yr[i] + pr * car - pi * cai;
            xi[i] = yi[i] + pr * cai + pi * car;
            float tt = pr * lr - pi * li;
            pi = pr * li + pi * lr;
            pr = tt;
        }

        if (lane == 31) g_carry[(b * NCH + chunkL) * ND + n] = make_float2(sr, si);

        float2* gb = g_bu + ((size_t)(b * ND + n)) * LS + l0;
        if (!rev) {
            *(float4*)(gb + lane * 4)     = make_float4(xr[0], xi[0], xr[1], xi[1]);
            *(float4*)(gb + lane * 4 + 2) = make_float4(xr[2], xi[2], xr[3], xi[3]);
        } else {
            *(float4*)(gb + pbL)     = make_float4(xr[3], xi[3], xr[2], xi[2]);
            *(float4*)(gb + pbL + 2) = make_float4(xr[1], xi[1], xr[0], xi[0]);
        }
    }
}

// ---------------- Scan phase B: parallel warp scan over chunks ---------------
__global__ __launch_bounds__(256)
void scanB(const float* __restrict__ nu_log, const float* __restrict__ th_log) {
    int t = blockIdx.x * 256 + threadIdx.x;
    int lane = t & 31;
    int w = t >> 5;
    int n = w & (ND - 1), b = w >> 9;

    float lr, li;
    lam_of(n, nu_log, th_log, lr, li);
    float fr = lr, fi = li;
#pragma unroll
    for (int s = 0; s < 7; s++) {
        float t2 = fr * fr - fi * fi;
        fi = 2.f * fr * fi;
        fr = t2;
    }

    float2 s2 = g_carry[(b * NCH + lane) * ND + n];
    float sr = s2.x, si = s2.y;
#pragma unroll
    for (int s = 1; s < 32; s <<= 1) {
        float pr_ = __shfl_up_sync(0xffffffffu, sr, s);
        float pi_ = __shfl_up_sync(0xffffffffu, si, s);
        if (lane >= s) {
            sr = fmaf(fr, pr_, fmaf(-fi, pi_, sr));
            si = fmaf(fr, pi_, fmaf( fi, pr_, si));
        }
        float nfr = fr * fr - fi * fi;
        fi = 2.f * fr * fi;
        fr = nfr;
    }
    float er = __shfl_up_sync(0xffffffffu, sr, 1);
    float ei = __shfl_up_sync(0xffffffffu, si, 1);
    if (lane == 0) { er = 0.f; ei = 0.f; }
    g_cin[(b * NCH + lane) * ND + n] = make_float2(er, ei);
}

// -------- GEMM2 (R7 skeleton, 2-stage) + fused carry-fix/mask/round ---------
__global__ __launch_bounds__(256)
void gemm_y_mma(const int* __restrict__ lengths, float* __restrict__ out) {
    extern __shared__ float sm[];
    uint32_t sA = (uint32_t)__cvta_generic_to_shared(sm);
    uint32_t sB = sA + 2 * ABYTES;
    float* As = sm;

    int tid = threadIdx.x, wid = tid >> 5, lane = tid & 31;
    int g = lane >> 2, t = lane & 3;
    int wm = wid >> 1, wn = wid & 1;
    int j0 = blockIdx.x * 128;
    int b  = blockIdx.y >> 5;
    int l0 = (blockIdx.y & 31) * 128;

    const float* cb = g_ct + (size_t)j0 * 1024;
    int len = lengths[b];

    int lr8 = lane & 7, lm = lane >> 3;
    int rsel = (lm & 1) * 8, csel = (lm >> 1) * 4;
    uint32_t aB[2], bBp[4];
#pragma unroll
    for (int mi = 0; mi < 2; mi++)
        aB[mi] = sA + ((wm * 32 + mi * 16 + rsel + lr8) * PAD + csel) * 4;
#pragma unroll
    for (int p = 0; p < 4; p++)
        bBp[p] = sB + ((wn * 64 + p * 16 + rsel + lr8) * PAD + csel) * 4;

    int crow = tid >> 3, cc4 = tid & 7;
    int ani = tid >> 7;
    int ali = tid & 127;
    bool maskme = (l0 + ali) >= len;

    float acc[2][8][4];
#pragma unroll
    for (int mi = 0; mi < 2; mi++)
#pragma unroll
        for (int ni = 0; ni < 8; ni++)
#pragma unroll
            for (int q = 0; q < 4; q++) acc[mi][ni][q] = 0.f;

    float2 pf[8];

#define G2_BLOAD(c_, buf_)                                                     \
    {                                                                          \
        int k0_ = (c_) * 32;                                                   \
        uint32_t db_ = sB + (buf_) * ABYTES;                                   \
        _Pragma("unroll")                                                      \
        for (int i_ = 0; i_ < 4; i_++) {                                       \
            int r_ = crow + 32 * i_;                                           \
            cpa16(db_ + (r_ * PAD + cc4 * 4) * 4,                              \
                  cb + (size_t)r_ * 1024 + k0_ + cc4 * 4);                     \
        }                                                                      \
        CP_COMMIT();                                                           \
    }
#define G2_ALDG(c_)                                                            \
    {                                                                          \
        int nb_ = (c_) * 16;                                                   \
        _Pragma("unroll")                                                      \
        for (int i_ = 0; i_ < 8; i_++)                                         \
            pf[i_] = g_bu[((size_t)(b * ND + nb_ + ani + 2 * i_)) * LS + l0 + ali]; \
    }
// carry-fix + mask + tf32 round + STS, per-iteration temps (validated in R8)
#define G2_FIX_ASTS(c_, buf_)                                                  \
    {                                                                          \
        bool rev_ = ((c_) >= 16);                                              \
        int chunk_ = rev_ ? 31 - (l0 >> 7) : (l0 >> 7);                        \
        int pos_   = rev_ ? 127 - ali : ali;                                   \
        const float2* cinp_ = &g_cin[(b * NCH + chunk_) * ND];                 \
        float* ab_ = As + (buf_) * (128 * PAD);                                \
        _Pragma("unroll")                                                      \
        for (int i_ = 0; i_ < 8; i_++) {                                       \
            int n_ = (c_) * 16 + ani + 2 * i_;                                 \
            float2 ci_ = cinp_[n_];                                            \
            float2 pw_ = g_pw[n_ * 128 + pos_];                                \
            float xr_ = pf[i_].x + pw_.x * ci_.x - pw_.y * ci_.y;              \
            float xi_ = pf[i_].y + pw_.x * ci_.y + pw_.y * ci_.x;              \
            if (maskme) { xr_ = 0.f; xi_ = 0.f; }                              \
            *(float2*)&ab_[ali * PAD + 2 * (ani + 2 * i_)] =                   \
                make_float2(tf32r(xr_), tf32r(xi_));                           \
        }                                                                      \
    }

    G2_BLOAD(0, 0);
    G2_ALDG(0);
    G2_FIX_ASTS(0, 0);
    CP_WAIT(0);
    __syncthreads();

    for (int c = 0; c < 32; c++) {
        int buf = c & 1;
        if (c < 31) { G2_BLOAD(c + 1, buf ^ 1); G2_ALDG(c + 1); }
        uint32_t boff = buf * ABYTES;
#pragma unroll
        for (int ks = 0; ks < 4; ks++) {
            int kb4 = ks * 32;
            uint32_t a0[4], a1[4];
            ldsm4(a0, aB[0] + boff + kb4);
            ldsm4(a1, aB[1] + boff + kb4);
#pragma unroll
            for (int p = 0; p < 4; p++) {
                uint32_t bf[4];
                ldsm4(bf, bBp[p] + boff + kb4);
                mma8(acc[0][2 * p],     a0, bf[0], bf[2]);
                mma8(acc[1][2 * p],     a1, bf[0], bf[2]);
                mma8(acc[0][2 * p + 1], a0, bf[1], bf[3]);
                mma8(acc[1][2 * p + 1], a1, bf[1], bf[3]);
            }
        }
        if (c < 31) { G2_FIX_ASTS(c + 1, buf ^ 1); CP_WAIT(0); }
        __syncthreads();
    }

#pragma unroll
    for (int mi = 0; mi < 2; mi++) {
        int l_lo = l0 + wm * 32 + mi * 16 + g;
        int l_hi = l_lo + 8;
#pragma unroll
        for (int ni = 0; ni < 8; ni++) {
            int j = j0 + wn * 64 + ni * 8 + 2 * t;
            *(float2*)&out[((size_t)b * LS + l_lo) * HD + j] =
                make_float2(acc[mi][ni][0], acc[mi][ni][1]);
            *(float2*)&out[((size_t)b * LS + l_hi) * HD + j] =
                make_float2(acc[mi][ni][2], acc[mi][ni][3]);
        }
    }
}

extern "C" void kernel_launch(void* const* d_in, const int* in_sizes, int n_in,
                              void* d_out, int out_size) {
    const float* u         = (const float*)d_in[0];
    const int*   lengths   = (const int*)d_in[1];
    const float* nu_log    = (const float*)d_in[2];
    const float* theta_log = (const float*)d_in[3];
    const float* Bw        = (const float*)d_in[4];
    const float* Cw        = (const float*)d_in[5];
    float* out = (float*)d_out;

    static int attr_set = 0;
    if (!attr_set) {
        cudaFuncSetAttribute(gemm_bu_mma, cudaFuncAttributeMaxDynamicSharedMemorySize, 4 * ABYTES);
        cudaFuncSetAttribute(gemm_y_mma,  cudaFuncAttributeMaxDynamicSharedMemorySize, 4 * ABYTES);
        attr_set = 1;
    }

    prep_u<<<4096, 256>>>(u);
    bt_prep<<<2048, 256>>>(Bw);
    cc_prep<<<2048, 256>>>(Cw);
    pw_prep<<<256, 256>>>(nu_log, theta_log);

    dim3 g1(1024 / 128, (BS * LS) / 128);   // (8, 256)
    gemm_bu_mma<<<g1, 256, 4 * ABYTES>>>(lengths, nu_log, theta_log);

    scanB<<<512, 256>>>(nu_log, theta_log);

    dim3 g2(HD / 128, (BS * LS) / 128);     // (4, 256)
    gemm_y_mma<<<g2, 256, 4 * ABYTES>>>(lengths, out);
}

// round 17
// speedup vs baseline: 1.0729x; 1.0729x over previous
#include <cuda_runtime.h>
#include <math.h>
#include <stdint.h>

#define HD 512
#define ND 512
#define BS 8
#define LS 4096
#define NHALF 256
#define NCH 32
#define CHL 128
#define PAD 36
#define ABYTES (128 * PAD * 4)

// Scratch buffers.
__device__ float2 g_bu[(size_t)BS * ND * LS];      // Bu / x, [b][n][l]
__device__ float2 g_carry[BS * NCH * ND];
__device__ float2 g_cin[BS * NCH * ND];
__device__ float  g_bt[(size_t)1024 * 512];        // B'[n'=2n+c][h], tf32
__device__ float  g_ct[(size_t)512 * 1024];        // Cc[j][k'=2n+c] = (C0,-C1), tf32

// ---------------------------------------------------------------- helpers ---
__device__ __forceinline__ float tf32r(float f) {
    uint32_t t;
    asm("cvt.rna.tf32.f32 %0, %1;" : "=r"(t) : "f"(f));
    return __uint_as_float(t);
}
__device__ __forceinline__ void mma8(float* d, const uint32_t* a, uint32_t b0, uint32_t b1) {
    asm volatile(
        "mma.sync.aligned.m16n8k8.row.col.f32.tf32.tf32.f32 "
        "{%0,%1,%2,%3}, {%4,%5,%6,%7}, {%8,%9}, {%0,%1,%2,%3};"
        : "+f"(d[0]), "+f"(d[1]), "+f"(d[2]), "+f"(d[3])
        : "r"(a[0]), "r"(a[1]), "r"(a[2]), "r"(a[3]), "r"(b0), "r"(b1));
}
__device__ __forceinline__ void ldsm4(uint32_t* r, uint32_t addr) {
    asm volatile("ldmatrix.sync.aligned.m8n8.x4.shared.b16 {%0,%1,%2,%3}, [%4];"
                 : "=r"(r[0]), "=r"(r[1]), "=r"(r[2]), "=r"(r[3]) : "r"(addr));
}
__device__ __forceinline__ void cpa16(uint32_t dst, const float* src) {
    asm volatile("cp.async.cg.shared.global [%0], [%1], 16;" :: "r"(dst), "l"(src));
}
#define CP_COMMIT() asm volatile("cp.async.commit_group;")
#define CP_WAIT(N)  asm volatile("cp.async.wait_group %0;" :: "n"(N))

__device__ __forceinline__ void lam_of(int n, const float* __restrict__ nu_log,
                                       const float* __restrict__ th_log,
                                       float& lr, float& li) {
    float nu  = expf(nu_log[n]);
    float mag = expf(-nu);
    float th  = expf(th_log[n]);
    float s, c;
    sincosf(th, &s, &c);
    lr = mag * c;
    li = mag * s;
}

// ---------------------------------------------------------------- preps -----
__global__ __launch_bounds__(256)
void bt_prep(const float* __restrict__ Bw) {
    int idx = blockIdx.x * 256 + threadIdx.x;
    int h  = idx & 511;
    int np = idx >> 9;
    g_bt[(size_t)np * 512 + h] = tf32r(Bw[(size_t)h * 1024 + np]);
}
__global__ __launch_bounds__(256)
void cc_prep(const float* __restrict__ Cw) {
    int idx = blockIdx.x * 256 + threadIdx.x;
    int j  = idx & 511;
    int kp = idx >> 9;
    int n  = kp >> 1, c = kp & 1;
    float v = Cw[(size_t)c * HD * ND + (size_t)n * ND + j];
    g_ct[(size_t)j * 1024 + kp] = tf32r(c ? -v : v);
}

// -------- GEMM1 + fused scanA: raw-u A operand (truncated tf32 in HMMA) -----
__global__ __launch_bounds__(256)
void gemm_bu_mma(const float* __restrict__ u, const int* __restrict__ lengths,
                 const float* __restrict__ nu_log, const float* __restrict__ th_log) {
    extern __shared__ float sm[];
    uint32_t sA = (uint32_t)__cvta_generic_to_shared(sm);
    uint32_t sB = sA + 2 * ABYTES;

    int tid = threadIdx.x, wid = tid >> 5, lane = tid & 31;
    int g = lane >> 2, t = lane & 3;
    int wm = wid >> 1, wn = wid & 1;
    int np0 = blockIdx.x * 128;
    int b   = blockIdx.y >> 5;
    int l0  = (blockIdx.y & 31) * 128;

    const float* ua = u + ((size_t)b * LS + l0) * HD;
    const float* bb = g_bt + (size_t)np0 * 512;

    int lr8 = lane & 7, lm = lane >> 3;
    int rsel = (lm & 1) * 8, csel = (lm >> 1) * 4;
    uint32_t aB[2], bBp[4];
#pragma unroll
    for (int mi = 0; mi < 2; mi++)
        aB[mi] = sA + ((wm * 32 + mi * 16 + rsel + lr8) * PAD + csel) * 4;
#pragma unroll
    for (int p = 0; p < 4; p++)
        bBp[p] = sB + ((wn * 64 + p * 16 + rsel + lr8) * PAD + csel) * 4;

    int crow = tid >> 3, cc4 = tid & 7;

    float acc[2][8][4];
#pragma unroll
    for (int mi = 0; mi < 2; mi++)
#pragma unroll
        for (int ni = 0; ni < 8; ni++)
#pragma unroll
            for (int q = 0; q < 4; q++) acc[mi][ni][q] = 0.f;

#define G1_LOAD(c_, buf_)                                                      \
    {                                                                          \
        int k0_ = (c_) * 32;                                                   \
        uint32_t da_ = sA + (buf_) * ABYTES, db_ = sB + (buf_) * ABYTES;       \
        _Pragma("unroll")                                                      \
        for (int i_ = 0; i_ < 4; i_++) {                                       \
            int r_ = crow + 32 * i_;                                           \
            cpa16(da_ + (r_ * PAD + cc4 * 4) * 4,                              \
                  ua + (size_t)r_ * HD + k0_ + cc4 * 4);                       \
            cpa16(db_ + (r_ * PAD + cc4 * 4) * 4,                              \
                  bb + (size_t)r_ * 512 + k0_ + cc4 * 4);                      \
        }                                                                      \
        CP_COMMIT();                                                           \
    }

    G1_LOAD(0, 0);
    for (int c = 0; c < 16; c++) {
        int buf = c & 1;
        if (c < 15) { G1_LOAD(c + 1, buf ^ 1); CP_WAIT(1); }
        else        { CP_WAIT(0); }
        __syncthreads();
        uint32_t boff = buf * ABYTES;
#pragma unroll
        for (int ks = 0; ks < 4; ks++) {
            int kb4 = ks * 32;
            uint32_t a0[4], a1[4];
            ldsm4(a0, aB[0] + boff + kb4);
            ldsm4(a1, aB[1] + boff + kb4);
#pragma unroll
            for (int p = 0; p < 4; p++) {
                uint32_t bf[4];
                ldsm4(bf, bBp[p] + boff + kb4);
                mma8(acc[0][2 * p],     a0, bf[0], bf[2]);
                mma8(acc[1][2 * p],     a1, bf[0], bf[2]);
                mma8(acc[0][2 * p + 1], a0, bf[1], bf[3]);
                mma8(acc[1][2 * p + 1], a1, bf[1], bf[3]);
            }
        }
        __syncthreads();
    }

    // ---- stage masked (re,im) tile in smem: tile[n_local][l_local] ----
    float2* tile = (float2*)sm;          // 64 rows x stride 132 float2 = 66KB
    int len = lengths[b];
#pragma unroll
    for (int mi = 0; mi < 2; mi++) {
        int l_lo = wm * 32 + mi * 16 + g;
        int l_hi = l_lo + 8;
        bool v0 = (l0 + l_lo) < len, v1 = (l0 + l_hi) < len;
#pragma unroll
        for (int ni = 0; ni < 8; ni++) {
            int nl = wn * 32 + ni * 4 + t;
            tile[nl * 132 + l_lo] = v0 ? make_float2(acc[mi][ni][0], acc[mi][ni][1])
                                       : make_float2(0.f, 0.f);
            tile[nl * 132 + l_hi] = v1 ? make_float2(acc[mi][ni][2], acc[mi][ni][3])
                                       : make_float2(0.f, 0.f);
        }
    }
    __syncthreads();

    // ---- fused scanA: each warp scans 8 n-rows of this 128-l chunk ----
    bool rev = (np0 >= 512);
    int chunkL = rev ? 31 - (l0 >> 7) : (l0 >> 7);
    int nbase = np0 >> 1;
#pragma unroll 1
    for (int r = 0; r < 8; r++) {
        int nl = wid * 8 + r;
        int n  = nbase + nl;
        float lr, li;
        lam_of(n, nu_log, th_log, lr, li);

        const float2* row = &tile[nl * 132];
        float cr[4], ci[4];
        int pbL = 124 - lane * 4;
        if (!rev) {
            float4 f0 = *(const float4*)&row[lane * 4];
            float4 f1 = *(const float4*)&row[lane * 4 + 2];
            cr[0] = f0.x; ci[0] = f0.y; cr[1] = f0.z; ci[1] = f0.w;
            cr[2] = f1.x; ci[2] = f1.y; cr[3] = f1.z; ci[3] = f1.w;
        } else {
            float4 f0 = *(const float4*)&row[pbL];
            float4 f1 = *(const float4*)&row[pbL + 2];
            cr[0] = f1.z; ci[0] = f1.w; cr[1] = f1.x; ci[1] = f1.y;
            cr[2] = f0.z; ci[2] = f0.w; cr[3] = f0.x; ci[3] = f0.y;
        }

        float yr[4], yi[4];
        yr[0] = cr[0]; yi[0] = ci[0];
#pragma unroll
        for (int i = 1; i < 4; i++) {
            yr[i] = fmaf(lr, yr[i - 1], fmaf(-li, yi[i - 1], cr[i]));
            yi[i] = fmaf(lr, yi[i - 1], fmaf( li, yr[i - 1], ci[i]));
        }

        float l2r = lr * lr - li * li, l2i = 2.f * lr * li;
        float fr  = l2r * l2r - l2i * l2i, fi = 2.f * l2r * l2i;

        float sr = yr[3], si = yi[3];
#pragma unroll
        for (int s = 1; s < 32; s <<= 1) {
            float pr_ = __shfl_up_sync(0xffffffffu, sr, s);
            float pi_ = __shfl_up_sync(0xffffffffu, si, s);
            if (lane >= s) {
                sr = fmaf(fr, pr_, fmaf(-fi, pi_, sr));
                si = fmaf(fr, pi_, fmaf( fi, pr_, si));
            }
            float nfr = fr * fr - fi * fi;
            fi = 2.f * fr * fi;
            fr = nfr;
        }
        float car = __shfl_up_sync(0xffffffffu, sr, 1);
        float cai = __shfl_up_sync(0xffffffffu, si, 1);
        if (lane == 0) { car = 0.f; cai = 0.f; }

        float pr = lr, pi = li;
        float xr[4], xi[4];
#pragma unroll
        for (int i = 0; i < 4; i++) {
            xr[i] = yr[i] + pr * car - pi * cai;
            xi[i] = yi[i] + pr * cai + pi * car;
            float tt = pr * lr - pi * li;
            pi = pr * li + pi * lr;
            pr = tt;
        }

        if (lane == 31) g_carry[(b * NCH + chunkL) * ND + n] = make_float2(sr, si);

        float2* gb = g_bu + ((size_t)(b * ND + n)) * LS + l0;
        if (!rev) {
            *(float4*)(gb + lane * 4)     = make_float4(xr[0], xi[0], xr[1], xi[1]);
            *(float4*)(gb + lane * 4 + 2) = make_float4(xr[2], xi[2], xr[3], xi[3]);
        } else {
            *(float4*)(gb + pbL)     = make_float4(xr[3], xi[3], xr[2], xi[2]);
            *(float4*)(gb + pbL + 2) = make_float4(xr[1], xi[1], xr[0], xi[0]);
        }
    }
}

// ---------------- Scan phase B: parallel warp scan over chunks ---------------
__global__ __launch_bounds__(256)
void scanB(const float* __restrict__ nu_log, const float* __restrict__ th_log) {
    int t = blockIdx.x * 256 + threadIdx.x;
    int lane = t & 31;
    int w = t >> 5;
    int n = w & (ND - 1), b = w >> 9;

    float lr, li;
    lam_of(n, nu_log, th_log, lr, li);
    float fr = lr, fi = li;
#pragma unroll
    for (int s = 0; s < 7; s++) {
        float t2 = fr * fr - fi * fi;
        fi = 2.f * fr * fi;
        fr = t2;
    }

    float2 s2 = g_carry[(b * NCH + lane) * ND + n];
    float sr = s2.x, si = s2.y;
#pragma unroll
    for (int s = 1; s < 32; s <<= 1) {
        float pr_ = __shfl_up_sync(0xffffffffu, sr, s);
        float pi_ = __shfl_up_sync(0xffffffffu, si, s);
        if (lane >= s) {
            sr = fmaf(fr, pr_, fmaf(-fi, pi_, sr));
            si = fmaf(fr, pi_, fmaf( fi, pr_, si));
        }
        float nfr = fr * fr - fi * fi;
        fi = 2.f * fr * fi;
        fr = nfr;
    }
    float er = __shfl_up_sync(0xffffffffu, sr, 1);
    float ei = __shfl_up_sync(0xffffffffu, si, 1);
    if (lane == 0) { er = 0.f; ei = 0.f; }
    g_cin[(b * NCH + lane) * ND + n] = make_float2(er, ei);
}

// ---------------- Scan phase C (writes tf32-rounded x) -----------------------
__global__ __launch_bounds__(256)
void scanC(const int* __restrict__ lengths, const float* __restrict__ nu_log,
           const float* __restrict__ th_log) {
    int gw   = (blockIdx.x * 256 + threadIdx.x) >> 5;
    int lane = threadIdx.x & 31;
    int chunk = gw & (NCH - 1);
    int n     = (gw >> 5) & (ND - 1);
    int b     = gw >> 14;

    float lr, li;
    lam_of(n, nu_log, th_log, lr, li);
    bool rev = (n >= NHALF);
    int len = lengths[b];

    float2* base = g_bu + ((size_t)(b * ND + n)) * LS;
    int t0 = chunk * CHL + lane * 4;
    int pb = LS - 4 - t0;

    float xr[4], xi[4];
    if (!rev) {
        float4 f0 = *(const float4*)(base + t0);
        float4 f1 = *(const float4*)(base + t0 + 2);
        xr[0] = f0.x; xi[0] = f0.y; xr[1] = f0.z; xi[1] = f0.w;
        xr[2] = f1.x; xi[2] = f1.y; xr[3] = f1.z; xi[3] = f1.w;
    } else {
        float4 f0 = *(const float4*)(base + pb);
        float4 f1 = *(const float4*)(base + pb + 2);
        xr[0] = f1.z; xi[0] = f1.w; xr[1] = f1.x; xi[1] = f1.y;
        xr[2] = f0.z; xi[2] = f0.w; xr[3] = f0.x; xi[3] = f0.y;
    }

    float2 C = g_cin[(b * NCH + chunk) * ND + n];

    float l2r = lr * lr - li * li, l2i = 2.f * lr * li;
    float f4r = l2r * l2r - l2i * l2i, f4i = 2.f * l2r * l2i;
    float p4r = 1.f, p4i = 0.f, qr = f4r, qi = f4i;
#pragma unroll
    for (int bit = 0; bit < 5; bit++) {
        if (lane & (1 << bit)) {
            float t2 = p4r * qr - p4i * qi;
            p4i = p4r * qi + p4i * qr;
            p4r = t2;
        }
        float t3 = qr * qr - qi * qi;
        qi = 2.f * qr * qi;
        qr = t3;
    }
    float pwr = p4r * lr - p4i * li;
    float pwi = p4r * li + p4i * lr;

#pragma unroll
    for (int i = 0; i < 4; i++) {
        xr[i] += pwr * C.x - pwi * C.y;
        xi[i] += pwr * C.y + pwi * C.x;
        float t2 = pwr * lr - pwi * li;
        pwi = pwr * li + pwi * lr;
        pwr = t2;
        int l = rev ? (LS - 1 - (t0 + i)) : (t0 + i);
        if (l >= len) { xr[i] = 0.f; xi[i] = 0.f; }
        xr[i] = tf32r(xr[i]);
        xi[i] = tf32r(xi[i]);
    }

    if (!rev) {
        *(float4*)(base + t0)     = make_float4(xr[0], xi[0], xr[1], xi[1]);
        *(float4*)(base + t0 + 2) = make_float4(xr[2], xi[2], xr[3], xi[3]);
    } else {
        *(float4*)(base + pb)     = make_float4(xr[3], xi[3], xr[2], xi[2]);
        *(float4*)(base + pb + 2) = make_float4(xr[1], xi[1], xr[0], xi[0]);
    }
}

// -------- GEMM2: y = x2 @ Cc via mma.sync + ldmatrix, pipelined (R7) --------
__global__ __launch_bounds__(256)
void gemm_y_mma(float* __restrict__ out) {
    extern __shared__ float sm[];
    uint32_t sA = (uint32_t)__cvta_generic_to_shared(sm);
    uint32_t sB = sA + 2 * ABYTES;
    float* As = sm;

    int tid = threadIdx.x, wid = tid >> 5, lane = tid & 31;
    int g = lane >> 2, t = lane & 3;
    int wm = wid >> 1, wn = wid & 1;
    int j0 = blockIdx.x * 128;
    int b  = blockIdx.y >> 5;
    int l0 = (blockIdx.y & 31) * 128;

    const float* cb = g_ct + (size_t)j0 * 1024;

    int lr8 = lane & 7, lm = lane >> 3;
    int rsel = (lm & 1) * 8, csel = (lm >> 1) * 4;
    uint32_t aB[2], bBp[4];
#pragma unroll
    for (int mi = 0; mi < 2; mi++)
        aB[mi] = sA + ((wm * 32 + mi * 16 + rsel + lr8) * PAD + csel) * 4;
#pragma unroll
    for (int p = 0; p < 4; p++)
        bBp[p] = sB + ((wn * 64 + p * 16 + rsel + lr8) * PAD + csel) * 4;

    int crow = tid >> 3, cc4 = tid & 7;
    int ani = tid >> 7;
    int ali = tid & 127;

    float acc[2][8][4];
#pragma unroll
    for (int mi = 0; mi < 2; mi++)
#pragma unroll
        for (int ni = 0; ni < 8; ni++)
#pragma unroll
            for (int q = 0; q < 4; q++) acc[mi][ni][q] = 0.f;

    float2 pf[8];

#define G2_BLOAD(c_, buf_)                                                     \
    {                                                                          \
        int k0_ = (c_) * 32;                                                   \
        uint32_t db_ = sB + (buf_) * ABYTES;                                   \
        _Pragma("unroll")                                                      \
        for (int i_ = 0; i_ < 4; i_++) {                                       \
            int r_ = crow + 32 * i_;                                           \
            cpa16(db_ + (r_ * PAD + cc4 * 4) * 4,                              \
                  cb + (size_t)r_ * 1024 + k0_ + cc4 * 4);                     \
        }                                                                      \
        CP_COMMIT();                                                           \
    }
#define G2_ALDG(c_)                                                            \
    {                                                                          \
        int nb_ = (c_) * 16;                                                   \
        _Pragma("unroll")                                                      \
        for (int i_ = 0; i_ < 8; i_++)                                         \
            pf[i_] = g_bu[((size_t)(b * ND + nb_ + ani + 2 * i_)) * LS + l0 + ali]; \
    }
#define G2_ASTS(buf_)                                                          \
    {                                                                          \
        float* ab_ = As + (buf_) * (128 * PAD);                                \
        _Pragma("unroll")                                                      \
        for (int i_ = 0; i_ < 8; i_++)                                         \
            *(float2*)&ab_[ali * PAD + 2 * (ani + 2 * i_)] = pf[i_];           \
    }

    G2_BLOAD(0, 0);
    G2_ALDG(0);
    G2_ASTS(0);
    CP_WAIT(0);
    __syncthreads();

    for (int c = 0; c < 32; c++) {
        int buf = c & 1;
        if (c < 31) { G2_BLOAD(c + 1, buf ^ 1); G2_ALDG(c + 1); }
        uint32_t boff = buf * ABYTES;
#pragma unroll
        for (int ks = 0; ks < 4; ks++) {
            int kb4 = ks * 32;
            uint32_t a0[4], a1[4];
            ldsm4(a0, aB[0] + boff + kb4);
            ldsm4(a1, aB[1] + boff + kb4);
#pragma unroll
            for (int p = 0; p < 4; p++) {
                uint32_t bf[4];
                ldsm4(bf, bBp[p] + boff + kb4);
                mma8(acc[0][2 * p],     a0, bf[0], bf[2]);
                mma8(acc[1][2 * p],     a1, bf[0], bf[2]);
                mma8(acc[0][2 * p + 1], a0, bf[1], bf[3]);
                mma8(acc[1][2 * p + 1], a1, bf[1], bf[3]);
            }
        }
        if (c < 31) { G2_ASTS(buf ^ 1); CP_WAIT(0); }
        __syncthreads();
    }

#pragma unroll
    for (int mi = 0; mi < 2; mi++) {
        int l_lo = l0 + wm * 32 + mi * 16 + g;
        int l_hi = l_lo + 8;
#pragma unroll
        for (int ni = 0; ni < 8; ni++) {
            int j = j0 + wn * 64 + ni * 8 + 2 * t;
            *(float2*)&out[((size_t)b * LS + l_lo) * HD + j] =
                make_float2(acc[mi][ni][0], acc[mi][ni][1]);
            *(float2*)&out[((size_t)b * LS + l_hi) * HD + j] =
                make_float2(acc[mi][ni][2], acc[mi][ni][3]);
        }
    }
}

extern "C" void kernel_launch(void* const* d_in, const int* in_sizes, int n_in,
                              void* d_out, int out_size) {
    const float* u         = (const float*)d_in[0];
    const int*   lengths   = (const int*)d_in[1];
    const float* nu_log    = (const float*)d_in[2];
    const float* theta_log = (const float*)d_in[3];
    const float* Bw        = (const float*)d_in[4];
    const float* Cw        = (const float*)d_in[5];
    float* out = (float*)d_out;

    static int attr_set = 0;
    if (!attr_set) {
        cudaFuncSetAttribute(gemm_bu_mma, cudaFuncAttributeMaxDynamicSharedMemorySize, 4 * ABYTES);
        cudaFuncSetAttribute(gemm_y_mma,  cudaFuncAttributeMaxDynamicSharedMemorySize, 4 * ABYTES);
        attr_set = 1;
    }

    bt_prep<<<2048, 256>>>(Bw);
    cc_prep<<<2048, 256>>>(Cw);

    dim3 g1(1024 / 128, (BS * LS) / 128);   // (8, 256)
    gemm_bu_mma<<<g1, 256, 4 * ABYTES>>>(u, lengths, nu_log, theta_log);

    scanB<<<512, 256>>>(nu_log, theta_log);
    scanC<<<16384, 256>>>(lengths, nu_log, theta_log);

    dim3 g2(HD / 128, (BS * LS) / 128);     // (4, 256)
    gemm_y_mma<<<g2, 256, 4 * ABYTES>>>(out);
}